// round 11
// baseline (speedup 1.0000x reference)
#include <cuda_runtime.h>
#include <stdint.h>

// ROISelect: per-row top-k(score) + ROI gather, two-phase, sort-free.
//   Phase A: 2 CTAs per row (grid 2x128, TPB=1024, 2 CTAs/SM => 64 warps/SM)
//            stream-scan half a row each, filter score >= 2.80 into a 16KB
//            smem stage, flush with ONE global atomic + coalesced writes.
//   Phase B: 128 CTAs: split-rank (2 threads per candidate over unique u64
//            keys value|~index, tf.nn.top_k tie order) + emit out[rank].
//            Exact 12-bit radix-select fallback if count outside [256,4096].

#define B_ROWS 128
#define N_COLS 131072
#define K_TOP  256
#define CAP    4096

#define A_TPB       1024
#define HALVES      2
#define HALF_ELEMS  (N_COLS / HALVES)            // 65536
#define A_V4        (HALF_ELEMS / 4 / A_TPB)     // 16 float4 per thread
#define A_GROUPS    4
#define A_GSIZE     (A_V4 / A_GROUPS)            // 4 float4 per load group
#define SCAP        2048                         // smem stage (16 KB)

#define B_TPB     1024
#define VEC_ITERS (N_COLS / 4 / B_TPB)           // 32 (fallback only)

__device__ unsigned long long g_cand[B_ROWS * CAP];
__device__ unsigned int       g_cnt[B_ROWS];     // zero at load; phase B resets

__device__ __forceinline__ unsigned int f2u(float f) {
    unsigned int b = __float_as_uint(f);
    return (b & 0x80000000u) ? ~b : (b | 0x80000000u);
}
__device__ __forceinline__ float u2f(unsigned int u) {
    unsigned int b = (u & 0x80000000u) ? (u ^ 0x80000000u) : ~u;
    return __uint_as_float(b);
}

// ---------------- Phase A: streaming filter, smem-staged ----------------
__global__ __launch_bounds__(A_TPB, 2)
void roisel_scan_kernel(const float* __restrict__ score)
{
    __shared__ unsigned long long stage[SCAP];
    __shared__ int s_cnt;
    __shared__ unsigned int s_base;

    const int tid  = threadIdx.x;
    const int half = blockIdx.x;
    const int row  = blockIdx.y;

    if (tid == 0) s_cnt = 0;
    __syncthreads();

    const float4* sc4 =
        (const float4*)(score + (size_t)row * N_COLS + (size_t)half * HALF_ELEMS);
    const int gbase = half * HALF_ELEMS;
    const float TGUESS = 2.80f;

    #pragma unroll
    for (int g = 0; g < A_GROUPS; ++g) {
        float4 v[A_GSIZE];
        #pragma unroll
        for (int u = 0; u < A_GSIZE; ++u)
            v[u] = sc4[tid + (g * A_GSIZE + u) * A_TPB];
        #pragma unroll
        for (int u = 0; u < A_GSIZE; ++u) {
            int ebase = gbase + (tid + (g * A_GSIZE + u) * A_TPB) * 4;
            float vals[4] = {v[u].x, v[u].y, v[u].z, v[u].w};
            #pragma unroll
            for (int c = 0; c < 4; ++c) {
                if (vals[c] >= TGUESS) {
                    int pos = atomicAdd(&s_cnt, 1);
                    if (pos < SCAP) {
                        unsigned int uu = __float_as_uint(vals[c]) | 0x80000000u;
                        stage[pos] = ((unsigned long long)uu << 32)
                                   | (unsigned int)~(unsigned int)(ebase + c);
                    }
                }
            }
        }
    }
    __syncthreads();

    int raw = s_cnt;
    int cnt = min(raw, SCAP);
    if (tid == 0) {
        unsigned int add = (unsigned int)raw;
        if (raw > SCAP) add += (1u << 20);       // force fallback in phase B
        s_base = atomicAdd(&g_cnt[row], add);
    }
    __syncthreads();

    unsigned int base = s_base;
    unsigned long long* dst = g_cand + (size_t)row * CAP;
    for (int i = tid; i < cnt; i += A_TPB) {
        unsigned int p = base + (unsigned int)i;
        if (p < CAP) dst[p] = stage[i];
    }
}

// ---------------- Phase B: split-rank + emit ----------------
__global__ __launch_bounds__(B_TPB, 1)
void roisel_rank_kernel(const float* __restrict__ score,
                        const float* __restrict__ roi,
                        float* __restrict__ out_roi,
                        float* __restrict__ out_score)
{
    __shared__ int s_bin;
    __shared__ int s_cnt;
    __shared__ unsigned int s_count;
    __shared__ unsigned int s_half[B_TPB];         // split-rank partials (4 KB)
    extern __shared__ unsigned long long cand[];   // CAP entries = 32 KB

    const int tid = threadIdx.x;
    const int row = blockIdx.x;

    // Read the counter ONCE, broadcast via smem, THEN reset (race-safe).
    if (tid == 0) s_count = g_cnt[row];
    __syncthreads();
    unsigned int count = s_count;
    if (tid == 0) g_cnt[row] = 0;                  // reset for next replay
    const unsigned long long* src = g_cand + (size_t)row * CAP;

    if (count >= K_TOP && count <= CAP) {
        for (unsigned int i = tid; i < count; i += B_TPB)
            cand[i] = src[i];
    } else {
        // ---------- Exact fallback: 12-bit radix select over the raw row ----------
        const float4* sc4 = (const float4*)(score + (size_t)row * N_COLS);
        unsigned int* hist  = (unsigned int*)cand;   // 4096 bins (aliased)
        unsigned int* sdata = hist + 4096;           // 1024 thread sums
        for (int i = tid; i < 4096; i += B_TPB) hist[i] = 0;
        if (tid == 0) s_cnt = 0;
        __syncthreads();

        for (int i = 0; i < VEC_ITERS; ++i) {
            float4 f = sc4[tid + i * B_TPB];
            float vals[4] = {f.x, f.y, f.z, f.w};
            #pragma unroll
            for (int c = 0; c < 4; ++c)
                atomicAdd(&hist[f2u(vals[c]) >> 20], 1u);
        }
        __syncthreads();

        unsigned int h0 = hist[4*tid+0], h1 = hist[4*tid+1];
        unsigned int h2 = hist[4*tid+2], h3 = hist[4*tid+3];
        sdata[tid] = h0 + h1 + h2 + h3;
        __syncthreads();
        for (int d = 1; d < B_TPB; d <<= 1) {        // inclusive suffix scan
            unsigned int vv = (tid + d < B_TPB) ? sdata[tid + d] : 0u;
            __syncthreads();
            sdata[tid] += vv;
            __syncthreads();
        }
        unsigned int Anext = (tid + 1 < B_TPB) ? sdata[tid + 1] : 0u;
        unsigned int cum3 = Anext + h3;
        unsigned int cum2 = cum3 + h2;
        unsigned int cum1 = cum2 + h1;
        unsigned int cum0 = cum1 + h0;
        if (cum3 >= K_TOP && Anext < K_TOP) s_bin = 4*tid + 3;
        if (cum2 >= K_TOP && cum3  < K_TOP) s_bin = 4*tid + 2;
        if (cum1 >= K_TOP && cum2  < K_TOP) s_bin = 4*tid + 1;
        if (cum0 >= K_TOP && cum1  < K_TOP) s_bin = 4*tid + 0;
        __syncthreads();
        unsigned int uthr = (unsigned int)s_bin << 20;
        __syncthreads();   // uthr read by all; hist region can be overwritten

        for (int i = 0; i < VEC_ITERS; ++i) {
            int v4i = tid + i * B_TPB;
            float4 f = sc4[v4i];
            int ebase = v4i * 4;
            float vals[4] = {f.x, f.y, f.z, f.w};
            #pragma unroll
            for (int c = 0; c < 4; ++c) {
                unsigned int u = f2u(vals[c]);
                if (u >= uthr) {
                    int pos = atomicAdd(&s_cnt, 1);
                    if (pos < CAP)
                        cand[pos] = ((unsigned long long)u << 32)
                                  | (unsigned int)~(unsigned int)(ebase + c);
                }
            }
        }
        __syncthreads();
        count = min((unsigned int)s_cnt, (unsigned int)CAP);
    }

    // Pad to even (a 0 key never outranks a real key: bit 63 set on real keys).
    if (tid == 0 && (count & 1u)) cand[count] = 0ULL;
    __syncthreads();
    const int pairs = (int)((count + 1u) >> 1);
    const ulonglong2* c2 = (const ulonglong2*)cand;

    if (count <= 512) {
        // ---------- Split rank: 2 threads per candidate ----------
        const int t     = tid & 511;
        const int which = tid >> 9;
        const int ph    = pairs >> 1;
        const int i0    = which ? ph : 0;
        const int i1    = which ? pairs : ph;
        unsigned int partial = 0;
        if (t < (int)count) {
            const unsigned long long key = cand[t];
            #pragma unroll 4
            for (int i = i0; i < i1; ++i) {
                ulonglong2 p = c2[i];
                partial += (p.x > key) + (p.y > key);
            }
        }
        s_half[tid] = partial;
        __syncthreads();

        if (tid < (int)count) {
            unsigned int rank = s_half[tid] + s_half[tid + 512];
            if (rank < K_TOP) {
                unsigned long long key = cand[tid];
                unsigned int u   = (unsigned int)(key >> 32);
                unsigned int idx = ~(unsigned int)key;
                const float4* r4 = (const float4*)roi;
                float4 rv = r4[(size_t)row * N_COLS + idx];
                out_score[row * K_TOP + rank] = u2f(u);
                ((float4*)out_roi)[row * K_TOP + rank] = rv;
            }
        }
    } else {
        // ---------- Serial rank (fallback-sized candidate sets only) ----------
        for (int c = tid; c < (int)count; c += B_TPB) {
            unsigned long long key = cand[c];
            int rank = 0;
            #pragma unroll 8
            for (int i = 0; i < pairs; ++i) {
                ulonglong2 p = c2[i];
                rank += (p.x > key) + (p.y > key);
            }
            if (rank < K_TOP) {
                unsigned int u   = (unsigned int)(key >> 32);
                unsigned int idx = ~(unsigned int)key;
                const float4* r4 = (const float4*)roi;
                float4 rv = r4[(size_t)row * N_COLS + idx];
                out_score[row * K_TOP + rank] = u2f(u);
                ((float4*)out_roi)[row * K_TOP + rank] = rv;
            }
        }
    }
}

extern "C" void kernel_launch(void* const* d_in, const int* in_sizes, int n_in,
                              void* d_out, int out_size) {
    (void)in_sizes; (void)n_in; (void)out_size;
    const float* score = (const float*)d_in[0];
    const float* roi   = (const float*)d_in[1];
    float* out_roi   = (float*)d_out;                               // [128,256,4]
    float* out_score = (float*)d_out + (size_t)B_ROWS * K_TOP * 4;  // [128,256]

    dim3 gridA(HALVES, B_ROWS);
    roisel_scan_kernel<<<gridA, A_TPB>>>(score);
    roisel_rank_kernel<<<B_ROWS, B_TPB, CAP * sizeof(unsigned long long)>>>(
        score, roi, out_roi, out_score);
}